// round 5
// baseline (speedup 1.0000x reference)
#include <cuda_runtime.h>
#include <cuda_bf16.h>
#include <math.h>
#include <stdint.h>
#include <stddef.h>

#define BATCH 4
#define SEQ 1024
#define DMODEL 1024
#define NH 16
#define HD 64
#define NROWS (BATCH*SEQ)          // 4096

#define PITCH 40                   // bf16 row pitch for 32-wide K tiles
#define PQ 72                      // pitch for 64-wide rows (Q/K/V head tiles)

// Scratch (static device globals: allowed; no runtime allocation)
__device__ float g_qp[NROWS*DMODEL];
__device__ float g_kp[NROWS*DMODEL];
__device__ float g_vp[NROWS*DMODEL];
__device__ float g_ctx[NROWS*DMODEL];

// ---------------------------------------------------------------------------
// Baseline-ISA tensor-core helpers (sm_80-level: ldmatrix + mma.sync bf16)
// ---------------------------------------------------------------------------
__device__ __forceinline__ uint32_t cvta_s(const void* p) {
    return (uint32_t)__cvta_generic_to_shared(p);
}

__device__ __forceinline__ void ldsm4(uint32_t* r, uint32_t addr) {
    asm volatile("ldmatrix.sync.aligned.m8n8.x4.shared.b16 {%0,%1,%2,%3}, [%4];"
                 : "=r"(r[0]), "=r"(r[1]), "=r"(r[2]), "=r"(r[3]) : "r"(addr));
}

__device__ __forceinline__ void ldsm4t(uint32_t* r, uint32_t addr) {
    asm volatile("ldmatrix.sync.aligned.m8n8.x4.trans.shared.b16 {%0,%1,%2,%3}, [%4];"
                 : "=r"(r[0]), "=r"(r[1]), "=r"(r[2]), "=r"(r[3]) : "r"(addr));
}

__device__ __forceinline__ void mma_bf16(float* c, const uint32_t* a, const uint32_t* b) {
    asm volatile(
        "mma.sync.aligned.m16n8k16.row.col.f32.bf16.bf16.f32 "
        "{%0,%1,%2,%3}, {%4,%5,%6,%7}, {%8,%9}, {%0,%1,%2,%3};"
        : "+f"(c[0]), "+f"(c[1]), "+f"(c[2]), "+f"(c[3])
        : "r"(a[0]), "r"(a[1]), "r"(a[2]), "r"(a[3]), "r"(b[0]), "r"(b[1]));
}

// bf16x3 split: pack (x,y) into hi bf16x2 and lo bf16x2 (lo = residual)
__device__ __forceinline__ void split2(float x, float y, uint32_t& hi, uint32_t& lo) {
    __nv_bfloat162 h = __floats2bfloat162_rn(x, y);
    float hx = __bfloat162float(h.x);
    float hy = __bfloat162float(h.y);
    __nv_bfloat162 l = __floats2bfloat162_rn(x - hx, y - hy);
    hi = *reinterpret_cast<uint32_t*>(&h);
    lo = *reinterpret_cast<uint32_t*>(&l);
}

__device__ __forceinline__ float2 unpack2(uint32_t hi, uint32_t lo) {
    __nv_bfloat162 h = *reinterpret_cast<__nv_bfloat162*>(&hi);
    __nv_bfloat162 l = *reinterpret_cast<__nv_bfloat162*>(&lo);
    return make_float2(__bfloat162float(h.x) + __bfloat162float(l.x),
                       __bfloat162float(h.y) + __bfloat162float(l.y));
}

// ---------------------------------------------------------------------------
// NT GEMM core (tensor cores, bf16x3): projections
// ---------------------------------------------------------------------------
__device__ __forceinline__ void gemm_nt_core(
    const float* __restrict__ A, int lda,
    const float* __restrict__ B, int ldb,
    float* __restrict__ C, int ldc,
    int nstages, float alpha, const float* __restrict__ bias,
    int row0, int col0)
{
    __shared__ __align__(16) __nv_bfloat16 sAh[128*PITCH];
    __shared__ __align__(16) __nv_bfloat16 sAl[128*PITCH];
    __shared__ __align__(16) __nv_bfloat16 sBh[128*PITCH];
    __shared__ __align__(16) __nv_bfloat16 sBl[128*PITCH];

    const int tid = threadIdx.x;
    const int w = tid >> 5, ln = tid & 31;
    const int wm = (w >> 2) * 64;
    const int wn = (w & 3) * 32;
    const int rg = tid >> 3;
    const int ck = tid & 7;

    const float* Ab = A + (size_t)(row0 + rg) * lda + ck * 4;
    const float* Bb = B + (size_t)(col0 + rg) * ldb + ck * 4;

    float acc[4][4][4];
#pragma unroll
    for (int i = 0; i < 4; i++)
#pragma unroll
        for (int j = 0; j < 4; j++)
#pragma unroll
            for (int t = 0; t < 4; t++) acc[i][j][t] = 0.f;

    const uint32_t uAh = cvta_s(sAh), uAl = cvta_s(sAl);
    const uint32_t uBh = cvta_s(sBh), uBl = cvta_s(sBl);

    float4 ar[4], br[4];
#pragma unroll
    for (int i = 0; i < 4; i++) {
        ar[i] = *(const float4*)(Ab + (size_t)i * 32 * lda);
        br[i] = *(const float4*)(Bb + (size_t)i * 32 * ldb);
    }

    for (int s = 0; s < nstages; s++) {
#pragma unroll
        for (int i = 0; i < 4; i++) {
            int r = rg + 32 * i;
            uint32_t h0, l0, h1, l1;
            split2(ar[i].x, ar[i].y, h0, l0);
            split2(ar[i].z, ar[i].w, h1, l1);
            int off = r * PITCH + ck * 4;
            *reinterpret_cast<uint32_t*>(&sAh[off])     = h0;
            *reinterpret_cast<uint32_t*>(&sAh[off + 2]) = h1;
            *reinterpret_cast<uint32_t*>(&sAl[off])     = l0;
            *reinterpret_cast<uint32_t*>(&sAl[off + 2]) = l1;
            split2(br[i].x, br[i].y, h0, l0);
            split2(br[i].z, br[i].w, h1, l1);
            *reinterpret_cast<uint32_t*>(&sBh[off])     = h0;
            *reinterpret_cast<uint32_t*>(&sBh[off + 2]) = h1;
            *reinterpret_cast<uint32_t*>(&sBl[off])     = l0;
            *reinterpret_cast<uint32_t*>(&sBl[off + 2]) = l1;
        }
        __syncthreads();

        if (s + 1 < nstages) {
            const float* An = Ab + (size_t)(s + 1) * 32;
            const float* Bn = Bb + (size_t)(s + 1) * 32;
#pragma unroll
            for (int i = 0; i < 4; i++) {
                ar[i] = *(const float4*)(An + (size_t)i * 32 * lda);
                br[i] = *(const float4*)(Bn + (size_t)i * 32 * ldb);
            }
        }

#pragma unroll
        for (int ks = 0; ks < 2; ks++) {
            uint32_t ah[4][4], al[4][4], bh[2][4], bl[2][4];
#pragma unroll
            for (int i = 0; i < 4; i++) {
                uint32_t off = (uint32_t)((wm + i * 16 + (ln & 15)) * PITCH) * 2
                             + (uint32_t)ks * 32 + (uint32_t)(ln >> 4) * 16;
                ldsm4(ah[i], uAh + off);
                ldsm4(al[i], uAl + off);
            }
#pragma unroll
            for (int g = 0; g < 2; g++) {
                uint32_t row = (uint32_t)(wn + g * 16 + ((ln >> 4) << 3) + (ln & 7));
                uint32_t off = row * PITCH * 2 + (uint32_t)ks * 32
                             + (uint32_t)((ln >> 3) & 1) * 16;
                ldsm4(bh[g], uBh + off);
                ldsm4(bl[g], uBl + off);
            }
#pragma unroll
            for (int i = 0; i < 4; i++)
#pragma unroll
                for (int j = 0; j < 4; j++) {
                    const uint32_t* bhj = &bh[j >> 1][(j & 1) * 2];
                    const uint32_t* blj = &bl[j >> 1][(j & 1) * 2];
                    mma_bf16(acc[i][j], ah[i], bhj);
                    mma_bf16(acc[i][j], ah[i], blj);
                    mma_bf16(acc[i][j], al[i], bhj);
                }
        }
        __syncthreads();
    }

#pragma unroll
    for (int i = 0; i < 4; i++) {
        int r = row0 + wm + i * 16 + (ln >> 2);
#pragma unroll
        for (int j = 0; j < 4; j++) {
            int c = col0 + wn + j * 8 + 2 * (ln & 3);
            float b0 = 0.f, b1 = 0.f;
            if (bias) { b0 = bias[c]; b1 = bias[c + 1]; }
            *(float2*)&C[(size_t)r * ldc + c] =
                make_float2(fmaf(alpha, acc[i][j][0], b0), fmaf(alpha, acc[i][j][1], b1));
            *(float2*)&C[(size_t)(r + 8) * ldc + c] =
                make_float2(fmaf(alpha, acc[i][j][2], b0), fmaf(alpha, acc[i][j][3], b1));
        }
    }
}

__global__ void __launch_bounds__(256, 1) proj_mma_kernel(
    const float* __restrict__ q, const float* __restrict__ k, const float* __restrict__ v,
    const float* __restrict__ Wq, const float* __restrict__ bq,
    const float* __restrict__ Wk, const float* __restrict__ bk,
    const float* __restrict__ Wv, const float* __restrict__ bv)
{
    const float *X, *W, *bias; float* O;
    if (blockIdx.z == 0)      { X = q; W = Wq; bias = bq; O = g_qp; }
    else if (blockIdx.z == 1) { X = k; W = Wk; bias = bk; O = g_kp; }
    else                      { X = v; W = Wv; bias = bv; O = g_vp; }
    gemm_nt_core(X, DMODEL, W, DMODEL, O, DMODEL, DMODEL / 32, 1.f, bias,
                 blockIdx.y * 128, blockIdx.x * 128);
}

// ---------------------------------------------------------------------------
// Fused attention: scores + mask + softmax + AV, one CTA = (b,h, 32 q-rows).
// Writes normalized attention directly to att (d_out), ctx to g_ctx.
// 256 threads = 8 warps: 2 m-rows (16 q each) x 4 n-slices (32 S-cols/tile).
// P kept in registers as bf16 hi/lo packed fragments across all 8 tiles.
// ---------------------------------------------------------------------------
__global__ void __launch_bounds__(256, 1) attn_fused_kernel(
    float* __restrict__ att, const unsigned char* __restrict__ masks)
{
    __shared__ __align__(16) __nv_bfloat16 sQh[32*PQ];
    __shared__ __align__(16) __nv_bfloat16 sQl[32*PQ];
    __shared__ __align__(16) __nv_bfloat16 sTh[128*PQ];   // K then V tiles
    __shared__ __align__(16) __nv_bfloat16 sTl[128*PQ];
    __shared__ float sred[4*32];

    const int z = blockIdx.y;              // b*16 + h
    const int b = z >> 4, h = z & 15;
    const int q0 = blockIdx.x * 32;

    const int tid = threadIdx.x;
    const int w = tid >> 5, ln = tid & 31;
    const int wm = (w >> 2) * 16;          // warp m-offset (0/16)
    const int nb = (w & 3) * 32;           // warp n-slice within 128-tile
    const int r_lo = wm + (ln >> 2);       // local q-row of c0,c1
    const int i0 = q0 + r_lo;              // global q-row

    const uint32_t uQh = cvta_s(sQh), uQl = cvta_s(sQl);
    const uint32_t uTh = cvta_s(sTh), uTl = cvta_s(sTl);

    // ---- load Q block (32 x 64) ----
    {
        const int row = tid >> 4, c = tid & 15;   // 16 rows/pass, 2 passes
#pragma unroll
        for (int i = 0; i < 2; i++) {
            int r = row + 16 * i;
            float4 v4 = *(const float4*)&g_qp[((size_t)b * SEQ + q0 + r) * DMODEL + h * HD + c * 4];
            uint32_t h0, l0, h1, l1;
            split2(v4.x, v4.y, h0, l0);
            split2(v4.z, v4.w, h1, l1);
            int off = r * PQ + c * 4;
            *reinterpret_cast<uint32_t*>(&sQh[off])     = h0;
            *reinterpret_cast<uint32_t*>(&sQh[off + 2]) = h1;
            *reinterpret_cast<uint32_t*>(&sQl[off])     = l0;
            *reinterpret_cast<uint32_t*>(&sQl[off + 2]) = l1;
        }
    }
    __syncthreads();

    // preload Q fragments (4 k16 chunks)
    uint32_t aqh[4][4], aql[4][4];
#pragma unroll
    for (int ks = 0; ks < 4; ks++) {
        uint32_t off = (uint32_t)((wm + (ln & 15)) * PQ) * 2
                     + (uint32_t)ks * 32 + (uint32_t)(ln >> 4) * 16;
        ldsm4(aqh[ks], uQh + off);
        ldsm4(aql[ks], uQl + off);
    }

    uint32_t Ph[8][8], Pl[8][8];           // packed bf16 P fragments
    float rs0 = 0.f, rs1 = 0.f;            // rowsums (rows r_lo, r_lo+8)

    const int trow = tid >> 4, tc = tid & 15;     // tile loader mapping

    // ================= Phase 1: S tiles -> exp -> P regs =================
#pragma unroll
    for (int nt = 0; nt < 8; nt++) {
        __syncthreads();
        // load K tile (128 x 64)
#pragma unroll
        for (int i = 0; i < 8; i++) {
            int r = trow + 16 * i;
            float4 v4 = *(const float4*)&g_kp[((size_t)b * SEQ + nt * 128 + r) * DMODEL + h * HD + tc * 4];
            uint32_t h0, l0, h1, l1;
            split2(v4.x, v4.y, h0, l0);
            split2(v4.z, v4.w, h1, l1);
            int off = r * PQ + tc * 4;
            *reinterpret_cast<uint32_t*>(&sTh[off])     = h0;
            *reinterpret_cast<uint32_t*>(&sTh[off + 2]) = h1;
            *reinterpret_cast<uint32_t*>(&sTl[off])     = l0;
            *reinterpret_cast<uint32_t*>(&sTl[off + 2]) = l1;
        }
        __syncthreads();

        float s[4][4];
#pragma unroll
        for (int j = 0; j < 4; j++)
#pragma unroll
            for (int t = 0; t < 4; t++) s[j][t] = 0.f;

#pragma unroll
        for (int ks = 0; ks < 4; ks++) {
            uint32_t bh[2][4], bl[2][4];
#pragma unroll
            for (int g = 0; g < 2; g++) {
                uint32_t row = (uint32_t)(nb + g * 16 + ((ln >> 4) << 3) + (ln & 7));
                uint32_t off = row * PQ * 2 + (uint32_t)ks * 32
                             + (uint32_t)((ln >> 3) & 1) * 16;
                ldsm4(bh[g], uTh + off);
                ldsm4(bl[g], uTl + off);
            }
#pragma unroll
            for (int j = 0; j < 4; j++) {
                const uint32_t* bhj = &bh[j >> 1][(j & 1) * 2];
                const uint32_t* blj = &bl[j >> 1][(j & 1) * 2];
                mma_bf16(s[j], aqh[ks], bhj);
                mma_bf16(s[j], aqh[ks], blj);
                mma_bf16(s[j], aql[ks], bhj);
            }
        }

        // mask + exp + pack
#pragma unroll
        for (int j = 0; j < 4; j++) {
            int col0 = nt * 128 + nb + j * 8 + 2 * (ln & 3);
            const unsigned char* mp = masks + ((size_t)b * SEQ + i0) * SEQ + col0;
            uchar2 ma = *(const uchar2*)mp;
            uchar2 mb = *(const uchar2*)(mp + 8 * SEQ);
            float e00 = ma.x ? 0.f : __expf(0.125f * s[j][0]);
            float e01 = ma.y ? 0.f : __expf(0.125f * s[j][1]);
            float e10 = mb.x ? 0.f : __expf(0.125f * s[j][2]);
            float e11 = mb.y ? 0.f : __expf(0.125f * s[j][3]);
            rs0 += e00 + e01;
            rs1 += e10 + e11;
            split2(e00, e01, Ph[nt][2 * j],     Pl[nt][2 * j]);
            split2(e10, e11, Ph[nt][2 * j + 1], Pl[nt][2 * j + 1]);
        }
    }

    // ================= rowsum reduce =================
    rs0 += __shfl_xor_sync(0xffffffffu, rs0, 1);
    rs0 += __shfl_xor_sync(0xffffffffu, rs0, 2);
    rs1 += __shfl_xor_sync(0xffffffffu, rs1, 1);
    rs1 += __shfl_xor_sync(0xffffffffu, rs1, 2);
    if ((ln & 3) == 0) {
        sred[(w & 3) * 32 + r_lo]     = rs0;
        sred[(w & 3) * 32 + r_lo + 8] = rs1;
    }
    __syncthreads();
    const float inv0 = 1.f / (sred[r_lo] + sred[32 + r_lo] + sred[64 + r_lo] + sred[96 + r_lo]);
    const float inv1 = 1.f / (sred[r_lo + 8] + sred[32 + r_lo + 8] + sred[64 + r_lo + 8] + sred[96 + r_lo + 8]);

    // ================= Phase 2: att write + P@V =================
    float ctx[8][4];
#pragma unroll
    for (int j = 0; j < 8; j++)
#pragma unroll
        for (int t = 0; t < 4; t++) ctx[j][t] = 0.f;

#pragma unroll
    for (int nt = 0; nt < 8; nt++) {
        __syncthreads();
        // load V tile (128 x 64) into the same buffer
#pragma unroll
        for (int i = 0; i < 8; i++) {
            int r = trow + 16 * i;
            float4 v4 = *(const float4*)&g_vp[((size_t)b * SEQ + nt * 128 + r) * DMODEL + h * HD + tc * 4];
            uint32_t h0, l0, h1, l1;
            split2(v4.x, v4.y, h0, l0);
            split2(v4.z, v4.w, h1, l1);
            int off = r * PQ + tc * 4;
            *reinterpret_cast<uint32_t*>(&sTh[off])     = h0;
            *reinterpret_cast<uint32_t*>(&sTh[off + 2]) = h1;
            *reinterpret_cast<uint32_t*>(&sTl[off])     = l0;
            *reinterpret_cast<uint32_t*>(&sTl[off + 2]) = l1;
        }
        __syncthreads();

        // write normalized attention for this tile
#pragma unroll
        for (int j = 0; j < 4; j++) {
            int col0 = nt * 128 + nb + j * 8 + 2 * (ln & 3);
            float2 e0 = unpack2(Ph[nt][2 * j],     Pl[nt][2 * j]);
            float2 e1 = unpack2(Ph[nt][2 * j + 1], Pl[nt][2 * j + 1]);
            *(float2*)&att[((size_t)z * SEQ + i0) * SEQ + col0] =
                make_float2(e0.x * inv0, e0.y * inv0);
            *(float2*)&att[((size_t)z * SEQ + i0 + 8) * SEQ + col0] =
                make_float2(e1.x * inv1, e1.y * inv1);
        }

        // P@V for this tile: warp's k-slice = rows [nb, nb+32) of the V tile
#pragma unroll
        for (int kc = 0; kc < 2; kc++) {
            uint32_t bh[4][4], bl[4][4];
#pragma unroll
            for (int g = 0; g < 4; g++) {
                uint32_t rk = (uint32_t)(nb + kc * 16 + (((ln >> 3) & 1) << 3) + (ln & 7));
                uint32_t nc = (uint32_t)(g * 16 + ((ln >> 4) << 3));
                uint32_t off = rk * PQ * 2 + nc * 2;
                ldsm4t(bh[g], uTh + off);
                ldsm4t(bl[g], uTl + off);
            }
            const uint32_t* aPh = &Ph[nt][kc * 4];
            const uint32_t* aPl = &Pl[nt][kc * 4];
#pragma unroll
            for (int j = 0; j < 8; j++) {
                const uint32_t* bhj = &bh[j >> 1][(j & 1) * 2];
                const uint32_t* blj = &bl[j >> 1][(j & 1) * 2];
                mma_bf16(ctx[j], aPh, bhj);
                mma_bf16(ctx[j], aPh, blj);
                mma_bf16(ctx[j], aPl, bhj);
            }
        }
    }

    // ================= cross-warp ctx reduce (k-slices) =================
    float* sctx = reinterpret_cast<float*>(sTh);   // 32x64 floats = 8KB
    __syncthreads();
#pragma unroll
    for (int c = 0; c < 4; c++) {
        if ((w & 3) == c) {
#pragma unroll
            for (int j = 0; j < 8; j++) {
                int col = j * 8 + 2 * (ln & 3);
                int o0 = r_lo * 64 + col;
                int o1 = (r_lo + 8) * 64 + col;
                if (c == 0) {
                    sctx[o0] = ctx[j][0]; sctx[o0 + 1] = ctx[j][1];
                    sctx[o1] = ctx[j][2]; sctx[o1 + 1] = ctx[j][3];
                } else {
                    sctx[o0] += ctx[j][0]; sctx[o0 + 1] += ctx[j][1];
                    sctx[o1] += ctx[j][2]; sctx[o1 + 1] += ctx[j][3];
                }
            }
        }
        __syncthreads();
    }

    // write ctx (normalized)
    {
        int row = tid >> 3, cb = (tid & 7) * 8;
        float inv = 1.f / (sred[row] + sred[32 + row] + sred[64 + row] + sred[96 + row]);
        float* dst = &g_ctx[((size_t)b * SEQ + q0 + row) * DMODEL + h * HD + cb];
#pragma unroll
        for (int c = 0; c < 8; c++) dst[c] = sctx[row * 64 + cb + c] * inv;
    }
}

// ---------------------------------------------------------------------------
// output = LayerNorm(qp + ctx) * g + b
// ---------------------------------------------------------------------------
__global__ void ln_kernel(float* __restrict__ out,
                          const float* __restrict__ gam,
                          const float* __restrict__ bet)
{
    __shared__ float reds[8];
    __shared__ float redq[8];
    __shared__ float stat[2];

    int row = blockIdx.x;
    const float* xq = g_qp + (size_t)row * DMODEL;
    const float* xc = g_ctx + (size_t)row * DMODEL;
    int j = threadIdx.x * 4;

    float4 a = *(const float4*)(xq + j);
    float4 c = *(const float4*)(xc + j);
    float x0 = a.x + c.x, x1 = a.y + c.y, x2 = a.z + c.z, x3 = a.w + c.w;

    float s = x0 + x1 + x2 + x3;
    float sq = x0 * x0 + x1 * x1 + x2 * x2 + x3 * x3;
#pragma unroll
    for (int o = 16; o; o >>= 1) {
        s += __shfl_xor_sync(0xffffffffu, s, o);
        sq += __shfl_xor_sync(0xffffffffu, sq, o);
    }
    if ((threadIdx.x & 31) == 0) { reds[threadIdx.x >> 5] = s; redq[threadIdx.x >> 5] = sq; }
    __syncthreads();
    if (threadIdx.x == 0) {
        float S = 0.f, Q = 0.f;
#pragma unroll
        for (int w = 0; w < 8; w++) { S += reds[w]; Q += redq[w]; }
        float mu = S * (1.0f / DMODEL);
        float var = Q * (1.0f / DMODEL) - mu * mu;
        stat[0] = mu;
        stat[1] = rsqrtf(var + 1e-6f);
    }
    __syncthreads();
    float mu = stat[0], r = stat[1];

    float4 g4 = *(const float4*)(gam + j);
    float4 b4 = *(const float4*)(bet + j);
    float4 o4;
    o4.x = (x0 - mu) * r * g4.x + b4.x;
    o4.y = (x1 - mu) * r * g4.y + b4.y;
    o4.z = (x2 - mu) * r * g4.z + b4.z;
    o4.w = (x3 - mu) * r * g4.w + b4.w;
    *(float4*)(out + (size_t)row * DMODEL + j) = o4;
}

// ---------------------------------------------------------------------------
extern "C" void kernel_launch(void* const* d_in, const int* in_sizes, int n_in,
                              void* d_out, int out_size)
{
    const float* q  = (const float*)d_in[0];
    const float* k  = (const float*)d_in[1];
    const float* v  = (const float*)d_in[2];
    const unsigned char* masks = (const unsigned char*)d_in[3];
    const float* Wq = (const float*)d_in[4];
    const float* bq = (const float*)d_in[5];
    const float* Wk = (const float*)d_in[6];
    const float* bk = (const float*)d_in[7];
    const float* Wv = (const float*)d_in[8];
    const float* bv = (const float*)d_in[9];
    const float* lng = (const float*)d_in[10];
    const float* lnb = (const float*)d_in[11];

    float* out = (float*)d_out;
    float* att = out + (size_t)BATCH * SEQ * DMODEL;

    proj_mma_kernel<<<dim3(DMODEL / 128, NROWS / 128, 3), 256>>>(
        q, k, v, Wq, bq, Wk, bk, Wv, bv);
    attn_fused_kernel<<<dim3(SEQ / 32, BATCH * NH), 256>>>(att, masks);
    ln_kernel<<<NROWS, 256>>>(out, lng, lnb);
}

// round 6
// speedup vs baseline: 1.2024x; 1.2024x over previous
#include <cuda_runtime.h>
#include <cuda_bf16.h>
#include <math.h>
#include <stdint.h>
#include <stddef.h>

#define BATCH 4
#define SEQ 1024
#define DMODEL 1024
#define NH 16
#define HD 64
#define NROWS (BATCH*SEQ)          // 4096

#define PITCH 40                   // bf16 row pitch for 32-wide K tiles
#define PITCHV 72                  // bf16 row pitch for 64-wide V tiles
#define SZB (128*PITCH*2)          // bytes per 128x32 bf16 sub-tile (10240)
#define PROJ_SMEM (8*SZB)          // 2 buffers x (Ah,Al,Bh,Bl) = 81920

// Scratch (static device globals: allowed; no runtime allocation)
__device__ float g_qp[NROWS*DMODEL];
__device__ float g_kp[NROWS*DMODEL];
__device__ float g_vp[NROWS*DMODEL];
__device__ float g_ctx[NROWS*DMODEL];
__device__ float g_rspart[64*1024*8];   // per-(head,row) 8 column-block partials
__device__ float g_rowinv[64*1024];     // 1/rowsum

// ---------------------------------------------------------------------------
// Baseline-ISA tensor-core helpers (sm_80-level: ldmatrix + mma.sync bf16)
// ---------------------------------------------------------------------------
__device__ __forceinline__ uint32_t cvta_s(const void* p) {
    return (uint32_t)__cvta_generic_to_shared(p);
}

__device__ __forceinline__ void ldsm4(uint32_t* r, uint32_t addr) {
    asm volatile("ldmatrix.sync.aligned.m8n8.x4.shared.b16 {%0,%1,%2,%3}, [%4];"
                 : "=r"(r[0]), "=r"(r[1]), "=r"(r[2]), "=r"(r[3]) : "r"(addr));
}

__device__ __forceinline__ void ldsm4t(uint32_t* r, uint32_t addr) {
    asm volatile("ldmatrix.sync.aligned.m8n8.x4.trans.shared.b16 {%0,%1,%2,%3}, [%4];"
                 : "=r"(r[0]), "=r"(r[1]), "=r"(r[2]), "=r"(r[3]) : "r"(addr));
}

__device__ __forceinline__ void mma_bf16(float* c, const uint32_t* a, const uint32_t* b) {
    asm volatile(
        "mma.sync.aligned.m16n8k16.row.col.f32.bf16.bf16.f32 "
        "{%0,%1,%2,%3}, {%4,%5,%6,%7}, {%8,%9}, {%0,%1,%2,%3};"
        : "+f"(c[0]), "+f"(c[1]), "+f"(c[2]), "+f"(c[3])
        : "r"(a[0]), "r"(a[1]), "r"(a[2]), "r"(a[3]), "r"(b[0]), "r"(b[1]));
}

__device__ __forceinline__ void split2(float x, float y, uint32_t& hi, uint32_t& lo) {
    __nv_bfloat162 h = __floats2bfloat162_rn(x, y);
    float hx = __bfloat162float(h.x);
    float hy = __bfloat162float(h.y);
    __nv_bfloat162 l = __floats2bfloat162_rn(x - hx, y - hy);
    hi = *reinterpret_cast<uint32_t*>(&h);
    lo = *reinterpret_cast<uint32_t*>(&l);
}

__device__ __forceinline__ void sts2(uint32_t addr, uint32_t a, uint32_t b) {
    asm volatile("st.shared.v2.b32 [%0], {%1,%2};" :: "r"(addr), "r"(a), "r"(b) : "memory");
}

// split + store one 128x32 fp32 tile (held in 4 float4 regs) to hi/lo smem
__device__ __forceinline__ void store_tile(uint32_t uh, uint32_t ul,
                                           const float4* v, int rg, int ck) {
#pragma unroll
    for (int i = 0; i < 4; i++) {
        int off2 = ((rg + 32 * i) * PITCH + ck * 4) * 2;   // byte offset
        uint32_t h0, l0, h1, l1;
        split2(v[i].x, v[i].y, h0, l0);
        split2(v[i].z, v[i].w, h1, l1);
        sts2(uh + off2, h0, h1);
        sts2(ul + off2, l0, l1);
    }
}

// ---------------------------------------------------------------------------
// Projections, double-buffered pipeline: qp = q @ Wq^T + bq  (z selects q/k/v)
// ---------------------------------------------------------------------------
__global__ void __launch_bounds__(256, 1) proj_mma_kernel(
    const float* __restrict__ q, const float* __restrict__ k, const float* __restrict__ v,
    const float* __restrict__ Wq, const float* __restrict__ bq,
    const float* __restrict__ Wk, const float* __restrict__ bk,
    const float* __restrict__ Wv, const float* __restrict__ bv)
{
    extern __shared__ __align__(16) char dynsm[];

    const float *X, *W, *bias; float* O;
    if (blockIdx.z == 0)      { X = q; W = Wq; bias = bq; O = g_qp; }
    else if (blockIdx.z == 1) { X = k; W = Wk; bias = bk; O = g_kp; }
    else                      { X = v; W = Wv; bias = bv; O = g_vp; }

    const int tid = threadIdx.x;
    const int w = tid >> 5, ln = tid & 31;
    const int wm = (w >> 2) * 64;
    const int wn = (w & 3) * 32;
    const int rg = tid >> 3;
    const int ck = tid & 7;
    const int row0 = blockIdx.y * 128, col0 = blockIdx.x * 128;

    const float* Ab = X + (size_t)(row0 + rg) * DMODEL + ck * 4;
    const float* Bb = W + (size_t)(col0 + rg) * DMODEL + ck * 4;

    const uint32_t sb = cvta_s(dynsm);

    float acc[4][4][4];
#pragma unroll
    for (int i = 0; i < 4; i++)
#pragma unroll
        for (int j = 0; j < 4; j++)
#pragma unroll
            for (int t = 0; t < 4; t++) acc[i][j][t] = 0.f;

    float4 ar[4], br[4];
#pragma unroll
    for (int i = 0; i < 4; i++) {
        ar[i] = *(const float4*)(Ab + (size_t)i * 32 * DMODEL);
        br[i] = *(const float4*)(Bb + (size_t)i * 32 * DMODEL);
    }
    store_tile(sb,           sb + SZB,     ar, rg, ck);
    store_tile(sb + 2 * SZB, sb + 3 * SZB, br, rg, ck);
    __syncthreads();

    const int NST = DMODEL / 32;
    for (int s = 0; s < NST; s++) {
        const uint32_t bc = sb + (uint32_t)(s & 1) * 4 * SZB;

        // prefetch next stage into regs (LDG latency covered by mma below)
        if (s + 1 < NST) {
            const float* An = Ab + (size_t)(s + 1) * 32;
            const float* Bn = Bb + (size_t)(s + 1) * 32;
#pragma unroll
            for (int i = 0; i < 4; i++) {
                ar[i] = *(const float4*)(An + (size_t)i * 32 * DMODEL);
                br[i] = *(const float4*)(Bn + (size_t)i * 32 * DMODEL);
            }
        }

        // compute on current buffer
#pragma unroll
        for (int ks = 0; ks < 2; ks++) {
            uint32_t ah[4][4], al[4][4], bh[2][4], bl[2][4];
#pragma unroll
            for (int i = 0; i < 4; i++) {
                uint32_t off = (uint32_t)((wm + i * 16 + (ln & 15)) * PITCH) * 2
                             + (uint32_t)ks * 32 + (uint32_t)(ln >> 4) * 16;
                ldsm4(ah[i], bc + off);
                ldsm4(al[i], bc + SZB + off);
            }
#pragma unroll
            for (int g = 0; g < 2; g++) {
                uint32_t row = (uint32_t)(wn + g * 16 + ((ln >> 4) << 3) + (ln & 7));
                uint32_t off = row * PITCH * 2 + (uint32_t)ks * 32
                             + (uint32_t)((ln >> 3) & 1) * 16;
                ldsm4(bh[g], bc + 2 * SZB + off);
                ldsm4(bl[g], bc + 3 * SZB + off);
            }
#pragma unroll
            for (int i = 0; i < 4; i++)
#pragma unroll
                for (int j = 0; j < 4; j++) {
                    const uint32_t* bhj = &bh[j >> 1][(j & 1) * 2];
                    const uint32_t* blj = &bl[j >> 1][(j & 1) * 2];
                    mma_bf16(acc[i][j], ah[i], bhj);
                    mma_bf16(acc[i][j], ah[i], blj);
                    mma_bf16(acc[i][j], al[i], bhj);
                }
        }

        // store next stage into the other buffer (overlaps mma via other warps)
        if (s + 1 < NST) {
            const uint32_t bn = sb + (uint32_t)((s + 1) & 1) * 4 * SZB;
            store_tile(bn,           bn + SZB,     ar, rg, ck);
            store_tile(bn + 2 * SZB, bn + 3 * SZB, br, rg, ck);
        }
        __syncthreads();
    }

#pragma unroll
    for (int i = 0; i < 4; i++) {
        int r = row0 + wm + i * 16 + (ln >> 2);
#pragma unroll
        for (int j = 0; j < 4; j++) {
            int c = col0 + wn + j * 8 + 2 * (ln & 3);
            float b0 = bias[c], b1 = bias[c + 1];
            *(float2*)&O[(size_t)r * DMODEL + c] =
                make_float2(acc[i][j][0] + b0, acc[i][j][1] + b1);
            *(float2*)&O[(size_t)(r + 8) * DMODEL + c] =
                make_float2(acc[i][j][2] + b0, acc[i][j][3] + b1);
        }
    }
}

// ---------------------------------------------------------------------------
// Scores + exp (unnormalized) + row partials.
// Writes P = mask ? 0 : exp(s/8) to att; row partials -> g_rspart.
// ---------------------------------------------------------------------------
__global__ void __launch_bounds__(256, 1) scores_exp_kernel(
    float* __restrict__ att, const unsigned char* __restrict__ masks)
{
    __shared__ __align__(16) __nv_bfloat16 sAh[128*PITCH];
    __shared__ __align__(16) __nv_bfloat16 sAl[128*PITCH];
    __shared__ __align__(16) __nv_bfloat16 sBh[128*PITCH];
    __shared__ __align__(16) __nv_bfloat16 sBl[128*PITCH];

    const int z = blockIdx.z, b = z >> 4, h = z & 15;
    const float* A  = g_qp + (size_t)b * SEQ * DMODEL + h * HD;
    const float* Bm = g_kp + (size_t)b * SEQ * DMODEL + h * HD;
    const int row0 = blockIdx.y * 128, col0 = blockIdx.x * 128;

    const int tid = threadIdx.x;
    const int w = tid >> 5, ln = tid & 31;
    const int wm = (w >> 2) * 64;
    const int wn = (w & 3) * 32;
    const int rg = tid >> 3;
    const int ck = tid & 7;

    const float* Ab = A + (size_t)(row0 + rg) * DMODEL + ck * 4;
    const float* Bb = Bm + (size_t)(col0 + rg) * DMODEL + ck * 4;

    float acc[4][4][4];
#pragma unroll
    for (int i = 0; i < 4; i++)
#pragma unroll
        for (int j = 0; j < 4; j++)
#pragma unroll
            for (int t = 0; t < 4; t++) acc[i][j][t] = 0.f;

    const uint32_t uAh = cvta_s(sAh), uAl = cvta_s(sAl);
    const uint32_t uBh = cvta_s(sBh), uBl = cvta_s(sBl);

    float4 ar[4], br[4];
#pragma unroll
    for (int i = 0; i < 4; i++) {
        ar[i] = *(const float4*)(Ab + (size_t)i * 32 * DMODEL);
        br[i] = *(const float4*)(Bb + (size_t)i * 32 * DMODEL);
    }

    for (int s = 0; s < 2; s++) {          // K = 64
        store_tile(uAh, uAl, ar, rg, ck);
        store_tile(uBh, uBl, br, rg, ck);
        __syncthreads();

        if (s == 0) {
#pragma unroll
            for (int i = 0; i < 4; i++) {
                ar[i] = *(const float4*)(Ab + 32 + (size_t)i * 32 * DMODEL);
                br[i] = *(const float4*)(Bb + 32 + (size_t)i * 32 * DMODEL);
            }
        }

#pragma unroll
        for (int ks = 0; ks < 2; ks++) {
            uint32_t ah[4][4], al[4][4], bh[2][4], bl[2][4];
#pragma unroll
            for (int i = 0; i < 4; i++) {
                uint32_t off = (uint32_t)((wm + i * 16 + (ln & 15)) * PITCH) * 2
                             + (uint32_t)ks * 32 + (uint32_t)(ln >> 4) * 16;
                ldsm4(ah[i], uAh + off);
                ldsm4(al[i], uAl + off);
            }
#pragma unroll
            for (int g = 0; g < 2; g++) {
                uint32_t row = (uint32_t)(wn + g * 16 + ((ln >> 4) << 3) + (ln & 7));
                uint32_t off = row * PITCH * 2 + (uint32_t)ks * 32
                             + (uint32_t)((ln >> 3) & 1) * 16;
                ldsm4(bh[g], uBh + off);
                ldsm4(bl[g], uBl + off);
            }
#pragma unroll
            for (int i = 0; i < 4; i++)
#pragma unroll
                for (int j = 0; j < 4; j++) {
                    const uint32_t* bhj = &bh[j >> 1][(j & 1) * 2];
                    const uint32_t* blj = &bl[j >> 1][(j & 1) * 2];
                    mma_bf16(acc[i][j], ah[i], bhj);
                    mma_bf16(acc[i][j], ah[i], blj);
                    mma_bf16(acc[i][j], al[i], bhj);
                }
        }
        __syncthreads();
    }

    // epilogue: exp + att write + row partials
    float rp0[4], rp1[4];
#pragma unroll
    for (int i = 0; i < 4; i++) { rp0[i] = 0.f; rp1[i] = 0.f; }

#pragma unroll
    for (int i = 0; i < 4; i++) {
        int r = wm + i * 16 + (ln >> 2);       // local row in [0,128)
        int gr = row0 + r;                      // row within head
#pragma unroll
        for (int j = 0; j < 4; j++) {
            int c = col0 + wn + j * 8 + 2 * (ln & 3);
            const unsigned char* mp = masks + ((size_t)b * SEQ + gr) * SEQ + c;
            uchar2 ma = *(const uchar2*)mp;
            uchar2 mb = *(const uchar2*)(mp + 8 * SEQ);
            float e00 = ma.x ? 0.f : __expf(0.125f * acc[i][j][0]);
            float e01 = ma.y ? 0.f : __expf(0.125f * acc[i][j][1]);
            float e10 = mb.x ? 0.f : __expf(0.125f * acc[i][j][2]);
            float e11 = mb.y ? 0.f : __expf(0.125f * acc[i][j][3]);
            rp0[i] += e00 + e01;
            rp1[i] += e10 + e11;
            *(float2*)&att[((size_t)z * SEQ + gr) * SEQ + c] = make_float2(e00, e01);
            *(float2*)&att[((size_t)z * SEQ + gr + 8) * SEQ + c] = make_float2(e10, e11);
        }
    }
    // reduce over the 4 lanes sharing a row (ln bits 0..1)
#pragma unroll
    for (int i = 0; i < 4; i++) {
        rp0[i] += __shfl_xor_sync(0xffffffffu, rp0[i], 1);
        rp0[i] += __shfl_xor_sync(0xffffffffu, rp0[i], 2);
        rp1[i] += __shfl_xor_sync(0xffffffffu, rp1[i], 1);
        rp1[i] += __shfl_xor_sync(0xffffffffu, rp1[i], 2);
    }
    __syncthreads();                         // smem reuse
    float* sred = reinterpret_cast<float*>(sAh);   // 4 x 128 floats
    if ((ln & 3) == 0) {
#pragma unroll
        for (int i = 0; i < 4; i++) {
            int r = wm + i * 16 + (ln >> 2);
            sred[(w & 3) * 128 + r] = rp0[i];
            sred[(w & 3) * 128 + r + 8] = rp1[i];
        }
    }
    __syncthreads();
    if (tid < 128) {
        float ssum = sred[tid] + sred[128 + tid] + sred[256 + tid] + sred[384 + tid];
        g_rspart[(((size_t)z * SEQ) + row0 + tid) * 8 + blockIdx.x] = ssum;
    }
}

// ---------------------------------------------------------------------------
// rowinv = 1 / sum(partials)
// ---------------------------------------------------------------------------
__global__ void rowinv_kernel()
{
    int r = blockIdx.x * 256 + threadIdx.x;          // 0..65535
    const float4* p = (const float4*)&g_rspart[(size_t)r * 8];
    float4 a = p[0], b = p[1];
    g_rowinv[r] = 1.f / (a.x + a.y + a.z + a.w + b.x + b.y + b.z + b.w);
}

// ---------------------------------------------------------------------------
// AV + normalization: reads unnormalized P from att, scales by rowinv,
// writes normalized att back, computes ctx = Pnorm @ V.
// ---------------------------------------------------------------------------
__global__ void __launch_bounds__(256, 1) av_mma_kernel(float* __restrict__ att)
{
    __shared__ __align__(16) __nv_bfloat16 sAh[128*PITCH];
    __shared__ __align__(16) __nv_bfloat16 sAl[128*PITCH];
    __shared__ __align__(16) __nv_bfloat16 sVh[32*PITCHV];
    __shared__ __align__(16) __nv_bfloat16 sVl[32*PITCHV];

    int z = blockIdx.z;
    int b = z >> 4, h = z & 15;
    float* A = att + (size_t)z * SEQ * SEQ;
    const float* V = g_vp + (size_t)b * SEQ * DMODEL + h * HD;
    float* C = g_ctx + (size_t)b * SEQ * DMODEL + h * HD;
    const int row0 = blockIdx.y * 128;

    const int tid = threadIdx.x;
    const int w = tid >> 5, ln = tid & 31;
    const int wm = (w >> 1) * 32;
    const int wn = (w & 1) * 32;
    const int rg = tid >> 3, ck = tid & 7;
    const int vr = tid >> 4, vc = tid & 15;

    float* Ab = A + (size_t)(row0 + rg) * SEQ + ck * 4;
    const float* Vb = V + (size_t)vr * DMODEL + vc * 4;

    float inv[4];
#pragma unroll
    for (int i = 0; i < 4; i++)
        inv[i] = g_rowinv[((size_t)z << 10) + row0 + rg + 32 * i];

    float acc[2][4][4];
#pragma unroll
    for (int i = 0; i < 2; i++)
#pragma unroll
        for (int j = 0; j < 4; j++)
#pragma unroll
            for (int t = 0; t < 4; t++) acc[i][j][t] = 0.f;

    const uint32_t uAh = cvta_s(sAh), uAl = cvta_s(sAl);
    const uint32_t uVh = cvta_s(sVh), uVl = cvta_s(sVl);

    float4 ar[4], vrg[2];
#pragma unroll
    for (int i = 0; i < 4; i++) {
        ar[i] = *(const float4*)(Ab + (size_t)i * 32 * SEQ);
        ar[i].x *= inv[i]; ar[i].y *= inv[i]; ar[i].z *= inv[i]; ar[i].w *= inv[i];
    }
#pragma unroll
    for (int i = 0; i < 2; i++) vrg[i] = *(const float4*)(Vb + (size_t)i * 16 * DMODEL);

    const int NSTAGES = SEQ / 32;
    for (int s = 0; s < NSTAGES; s++) {
        // write normalized att back + stage into smem
#pragma unroll
        for (int i = 0; i < 4; i++)
            *(float4*)(Ab + (size_t)s * 32 + (size_t)i * 32 * SEQ) = ar[i];
        store_tile(uAh, uAl, ar, rg, ck);
#pragma unroll
        for (int i = 0; i < 2; i++) {
            int r = vr + 16 * i;
            uint32_t h0, l0, h1, l1;
            split2(vrg[i].x, vrg[i].y, h0, l0);
            split2(vrg[i].z, vrg[i].w, h1, l1);
            int off2 = (r * PITCHV + vc * 4) * 2;
            sts2(uVh + off2, h0, h1);
            sts2(uVl + off2, l0, l1);
        }
        __syncthreads();

        if (s + 1 < NSTAGES) {
            const float* An = Ab + (size_t)(s + 1) * 32;
            const float* Vn = Vb + (size_t)(s + 1) * 32 * DMODEL;
#pragma unroll
            for (int i = 0; i < 4; i++) {
                ar[i] = *(const float4*)(An + (size_t)i * 32 * SEQ);
                ar[i].x *= inv[i]; ar[i].y *= inv[i]; ar[i].z *= inv[i]; ar[i].w *= inv[i];
            }
#pragma unroll
            for (int i = 0; i < 2; i++) vrg[i] = *(const float4*)(Vn + (size_t)i * 16 * DMODEL);
        }

#pragma unroll
        for (int ks = 0; ks < 2; ks++) {
            uint32_t ah[2][4], al[2][4], bh[2][4], bl[2][4];
#pragma unroll
            for (int i = 0; i < 2; i++) {
                uint32_t off = (uint32_t)((wm + i * 16 + (ln & 15)) * PITCH) * 2
                             + (uint32_t)ks * 32 + (uint32_t)(ln >> 4) * 16;
                ldsm4(ah[i], uAh + off);
                ldsm4(al[i], uAl + off);
            }
#pragma unroll
            for (int g = 0; g < 2; g++) {
                uint32_t rk = (uint32_t)(ks * 16 + (((ln >> 3) & 1) << 3) + (ln & 7));
                uint32_t nc = (uint32_t)(wn + g * 16 + ((ln >> 4) << 3));
                uint32_t off = rk * PITCHV * 2 + nc * 2;
                ldsm4t(bh[g], uVh + off);
                ldsm4t(bl[g], uVl + off);
            }
#pragma unroll
            for (int i = 0; i < 2; i++)
#pragma unroll
                for (int j = 0; j < 4; j++) {
                    const uint32_t* bhj = &bh[j >> 1][(j & 1) * 2];
                    const uint32_t* blj = &bl[j >> 1][(j & 1) * 2];
                    mma_bf16(acc[i][j], ah[i], bhj);
                    mma_bf16(acc[i][j], ah[i], blj);
                    mma_bf16(acc[i][j], al[i], bhj);
                }
        }
        __syncthreads();
    }

#pragma unroll
    for (int i = 0; i < 2; i++) {
        int r = row0 + wm + i * 16 + (ln >> 2);
#pragma unroll
        for (int j = 0; j < 4; j++) {
            int c = wn + j * 8 + 2 * (ln & 3);
            *(float2*)&C[(size_t)r * DMODEL + c] =
                make_float2(acc[i][j][0], acc[i][j][1]);
            *(float2*)&C[(size_t)(r + 8) * DMODEL + c] =
                make_float2(acc[i][j][2], acc[i][j][3]);
        }
    }
}

// ---------------------------------------------------------------------------
// output = LayerNorm(qp + ctx) * g + b
// ---------------------------------------------------------------------------
__global__ void ln_kernel(float* __restrict__ out,
                          const float* __restrict__ gam,
                          const float* __restrict__ bet)
{
    __shared__ float reds[8];
    __shared__ float redq[8];
    __shared__ float stat[2];

    int row = blockIdx.x;
    const float* xq = g_qp + (size_t)row * DMODEL;
    const float* xc = g_ctx + (size_t)row * DMODEL;
    int j = threadIdx.x * 4;

    float4 a = *(const float4*)(xq + j);
    float4 c = *(const float4*)(xc + j);
    float x0 = a.x + c.x, x1 = a.y + c.y, x2 = a.z + c.z, x3 = a.w + c.w;

    float s = x0 + x1 + x2 + x3;
    float sq = x0 * x0 + x1 * x1 + x2 * x2 + x3 * x3;
#pragma unroll
    for (int o = 16; o; o >>= 1) {
        s += __shfl_xor_sync(0xffffffffu, s, o);
        sq += __shfl_xor_sync(0xffffffffu, sq, o);
    }
    if ((threadIdx.x & 31) == 0) { reds[threadIdx.x >> 5] = s; redq[threadIdx.x >> 5] = sq; }
    __syncthreads();
    if (threadIdx.x == 0) {
        float S = 0.f, Q = 0.f;
#pragma unroll
        for (int w = 0; w < 8; w++) { S += reds[w]; Q += redq[w]; }
        float mu = S * (1.0f / DMODEL);
        float var = Q * (1.0f / DMODEL) - mu * mu;
        stat[0] = mu;
        stat[1] = rsqrtf(var + 1e-6f);
    }
    __syncthreads();
    float mu = stat[0], r = stat[1];

    float4 g4 = *(const float4*)(gam + j);
    float4 b4 = *(const float4*)(bet + j);
    float4 o4;
    o4.x = (x0 - mu) * r * g4.x + b4.x;
    o4.y = (x1 - mu) * r * g4.y + b4.y;
    o4.z = (x2 - mu) * r * g4.z + b4.z;
    o4.w = (x3 - mu) * r * g4.w + b4.w;
    *(float4*)(out + (size_t)row * DMODEL + j) = o4;
}

// ---------------------------------------------------------------------------
extern "C" void kernel_launch(void* const* d_in, const int* in_sizes, int n_in,
                              void* d_out, int out_size)
{
    const float* q  = (const float*)d_in[0];
    const float* k  = (const float*)d_in[1];
    const float* v  = (const float*)d_in[2];
    const unsigned char* masks = (const unsigned char*)d_in[3];
    const float* Wq = (const float*)d_in[4];
    const float* bq = (const float*)d_in[5];
    const float* Wk = (const float*)d_in[6];
    const float* bk = (const float*)d_in[7];
    const float* Wv = (const float*)d_in[8];
    const float* bv = (const float*)d_in[9];
    const float* lng = (const float*)d_in[10];
    const float* lnb = (const float*)d_in[11];

    float* out = (float*)d_out;
    float* att = out + (size_t)BATCH * SEQ * DMODEL;

    static int smem_set = 0;
    if (!smem_set) {
        cudaFuncSetAttribute(proj_mma_kernel,
                             cudaFuncAttributeMaxDynamicSharedMemorySize, PROJ_SMEM);
        smem_set = 1;
    }

    proj_mma_kernel<<<dim3(DMODEL / 128, NROWS / 128, 3), 256, PROJ_SMEM>>>(
        q, k, v, Wq, bq, Wk, bk, Wv, bv);
    scores_exp_kernel<<<dim3(SEQ / 128, SEQ / 128, BATCH * NH), 256>>>(att, masks);
    rowinv_kernel<<<256, 256>>>();
    av_mma_kernel<<<dim3(1, SEQ / 128, BATCH * NH), 256>>>(att);
    ln_kernel<<<NROWS, 256>>>(out, lng, lnb);
}